// round 13
// baseline (speedup 1.0000x reference)
#include <cuda_runtime.h>
#include <cuda_bf16.h>

#define Bsz 4
#define Nn 300
#define TOP 36
#define Cc 2048
#define Dd 2048
#define NROI (Bsz*TOP)
#define KSPLIT 16
#define KSEG (Cc / KSPLIT)   // 128

// ---------------- scratch (device globals, no allocation) ----------------
__device__ int   g_valid[NROI];
__device__ int   g_level[NROI];
__device__ int   g_dest[NROI];
__device__ int   g_ny[NROI], g_nx[NROI];
__device__ int   g_yi[NROI][28], g_xi[NROI][28];
__device__ float g_yw[NROI][28], g_xw[NROI][28];
__device__ int   g_order[NROI];
__device__ float g_part[KSPLIT][NROI][Dd];

// bf16 hi/lo decompositions of pooled features (tensor-core GEMM A operand)
__device__ __align__(16) __nv_bfloat16 g_Ph[NROI][Cc];
__device__ __align__(16) __nv_bfloat16 g_Pl[NROI][Cc];

__device__ __forceinline__ int level_size(int l) {
    return (l == 0) ? 100 : (l == 1) ? 50 : (l == 2) ? 25 : 13;
}

// split a,b into bf16 hi + bf16 residual, packed as bf16x2 words
__device__ __forceinline__ void split2(float a, float b, unsigned& h, unsigned& l) {
    __nv_bfloat16 ha = __float2bfloat16(a);
    __nv_bfloat16 hb = __float2bfloat16(b);
    float ra = a - __bfloat162float(ha);
    float rb = b - __bfloat162float(hb);
    __nv_bfloat162 H; H.x = ha; H.y = hb;
    __nv_bfloat162 L; L.x = __float2bfloat16(ra); L.y = __float2bfloat16(rb);
    h = *reinterpret_cast<unsigned*>(&H);
    l = *reinterpret_cast<unsigned*>(&L);
}

// Streaming separable axis table: 14 monotone samples -> merged (idx, weight)
// list (<=28 entries). Exactly replicates reference bilinear accumulation.
__device__ int build_axis(float start, float rlen, int Hs, int* gidx, float* gwt) {
    int   li[28];
    float lw[28];
    int n = 0;
    float step7  = rlen / 7.0f;
    float step14 = rlen / 14.0f;
    for (int i = 0; i < 14; i++) {
        float yy = start + (float)(i >> 1) * step7 + ((float)(i & 1) + 0.5f) * step14;
        if (yy < -1.0f || yy > (float)Hs) continue;
        float yc = fminf(fmaxf(yy, 0.0f), (float)Hs - 1.0f);
        int i0 = (int)floorf(yc);
        int i1 = min(i0 + 1, Hs - 1);
        float w = yc - (float)i0;
        float w0 = 1.0f - w;
        if (n > 0 && li[n-1] == i0)      lw[n-1] += w0;
        else if (n > 1 && li[n-2] == i0) lw[n-2] += w0;
        else { li[n] = i0; lw[n] = w0; n++; }
        if (n > 0 && li[n-1] == i1)      lw[n-1] += w;
        else if (n > 1 && li[n-2] == i1) lw[n-2] += w;
        else { li[n] = i1; lw[n] = w; n++; }
    }
    for (int t = 0; t < n; t++) { gidx[t] = li[t]; gwt[t] = lw[t]; }
    return n;
}

// ---------------- kernel 1: filter + sort + warp NMS + tables + dest ----------------
__global__ void select_kernel(const float* __restrict__ boxes,
                              const float* __restrict__ scores) {
    int b = blockIdx.x;
    int tid = threadIdx.x;
    __shared__ float ss[Nn];
    __shared__ float sx1[Nn], sy1[Nn], sx2[Nn], sy2[Nn];
    __shared__ int   s_selidx[TOP];
    __shared__ int   s_cnt;
    __shared__ int   s_M;
    __shared__ int   keys[TOP];

    const float* sc = scores + b * Nn;
    const float* bx = boxes + (size_t)b * Nn * 4;

    if (tid == 0) s_M = 0;
    for (int i = tid; i < Nn; i += blockDim.x) ss[i] = sc[i];
    __syncthreads();

    {
        int local = 0;
        for (int i = tid; i < Nn; i += blockDim.x) local += (ss[i] > 0.3f);
        #pragma unroll
        for (int o = 16; o; o >>= 1) local += __shfl_down_sync(0xffffffffu, local, o);
        if ((tid & 31) == 0 && local) atomicAdd(&s_M, local);
    }

    for (int i = tid; i < Nn; i += blockDim.x) {
        float si = ss[i];
        if (si > 0.3f) {
            int rank = 0;
            for (int j = 0; j < Nn; j++) {
                float sj = ss[j];
                rank += (sj > 0.3f) && ((sj > si) || (sj == si && j < i));
            }
            sx1[rank] = bx[i * 4 + 0];
            sy1[rank] = bx[i * 4 + 1];
            sx2[rank] = bx[i * 4 + 2];
            sy2[rank] = bx[i * 4 + 3];
        }
    }
    __syncthreads();

    int M = s_M;

    if (tid < 32) {
        int lane = tid;
        unsigned kmask = 0;
        #pragma unroll
        for (int s2 = 0; s2 < 10; s2++)
            if (lane + 32 * s2 < M) kmask |= (1u << s2);
        int cnt = 0;
        for (int i = 0; i < M; i++) {
            unsigned om = __shfl_sync(0xffffffffu, kmask, i & 31);
            if (!((om >> (i >> 5)) & 1u)) continue;
            if (lane == 0) s_selidx[cnt] = i;
            cnt++;
            if (cnt >= TOP) break;
            float x1 = sx1[i], y1 = sy1[i], x2 = sx2[i], y2 = sy2[i];
            float ai = (x2 - x1) * (y2 - y1);
            #pragma unroll
            for (int s2 = 0; s2 < 10; s2++) {
                int j = lane + 32 * s2;
                if (((kmask >> s2) & 1u) && j > i && j < M) {
                    float jx1 = sx1[j], jy1 = sy1[j], jx2 = sx2[j], jy2 = sy2[j];
                    float xx1 = fmaxf(x1, jx1);
                    float yy1 = fmaxf(y1, jy1);
                    float xx2 = fminf(x2, jx2);
                    float yy2 = fminf(y2, jy2);
                    float inter = fmaxf(xx2 - xx1, 0.0f) * fmaxf(yy2 - yy1, 0.0f);
                    float aj = (jx2 - jx1) * (jy2 - jy1);
                    float iou = inter / (ai + aj - inter);
                    if (iou > 0.7f) kmask &= ~(1u << s2);
                }
            }
        }
        if (lane == 0) s_cnt = cnt;
    }
    __syncthreads();

    if (tid < TOP) {
        int r = tid;
        int roi = b * TOP + r;
        int valid = 0, lvl = 0;
        if (r < s_cnt) {
            valid = 1;
            int i = s_selidx[r];
            float bx0 = sx1[i], bx1 = sy1[i], bx2 = sx2[i], bx3 = sy2[i];
            float dx = bx2 - bx0, dy = bx3 - bx1;
            float diag = sqrtf(dx * dx + dy * dy);
            float lf = floorf(4.0f + log2f(diag / 224.0f * 4.0f));
            lf = fminf(fmaxf(lf, 2.0f), 5.0f);
            lvl = (int)lf - 2;
            int Hs = level_size(lvl);
            float rw = fmaxf(bx2 - bx0, 1.0f);
            float rh = fmaxf(bx3 - bx1, 1.0f);
            g_ny[roi] = build_axis(bx1, rh, Hs, g_yi[roi], g_yw[roi]);
            g_nx[roi] = build_axis(bx0, rw, Hs, g_xi[roi], g_xw[roi]);
        } else {
            g_ny[roi] = 0;
            g_nx[roi] = 0;
        }
        g_valid[roi] = valid;
        g_level[roi] = lvl;
        keys[r] = valid ? (lvl * TOP + r) : (4 * TOP + r);
    }
    __syncthreads();
    if (tid < TOP) {
        int k = keys[tid];
        int d = 0;
        for (int q = 0; q < TOP; q++) d += (keys[q] < k);
        g_dest[b * TOP + tid] = d;
    }
}

// ---------------- kernel 1b: LPT ordering (slow level-0 rois first) ----------------
__global__ void schedule_kernel() {
    __shared__ int keys[NROI];
    int t = threadIdx.x;
    if (t < NROI) {
        int lvl = g_level[t];
        int img = t / TOP;
        keys[t] = g_valid[t] ? (lvl * 8 + img) : 1024;
    }
    __syncthreads();
    if (t < NROI) {
        int k = keys[t];
        int rank = 0;
        for (int j = 0; j < NROI; j++)
            rank += (keys[j] < k) || (keys[j] == k && j < t);
        g_order[rank] = t;
    }
}

// ---------------- kernel 2: ROI pooling (R6 tap-gather + inline bf16 hi/lo epilogue) ----------------
__global__ void pool_kernel(const float* __restrict__ f0, const float* __restrict__ f1,
                            const float* __restrict__ f2, const float* __restrict__ f3) {
    int roi  = g_order[blockIdx.x];
    int cblk = blockIdx.y;
    int tid  = threadIdx.x;

    if (!g_valid[roi]) {
        if (tid < 64) {
            int c = cblk * 64 + tid;
            g_Ph[roi][c] = __float2bfloat16(0.0f);
            g_Pl[roi][c] = __float2bfloat16(0.0f);
        }
        return;
    }

    __shared__ int   soff[784];
    __shared__ float swt[784];

    int lvl = g_level[roi];
    int Hs  = level_size(lvl);
    int HW  = Hs * Hs;
    const float* fm = (lvl == 0) ? f0 : (lvl == 1) ? f1 : (lvl == 2) ? f2 : f3;

    int ny = g_ny[roi], nx = g_nx[roi];
    int n = ny * nx;
    for (int k = tid; k < n; k += 256) {
        int a = k / nx;
        int q = k - a * nx;
        soff[k] = g_yi[roi][a] * Hs + g_xi[roi][q];
        swt[k]  = g_yw[roi][a] * g_xw[roi][q];
    }
    __syncthreads();

    int bimg = roi / TOP;
    int warp = tid >> 5, lane = tid & 31;
    #pragma unroll
    for (int q = 0; q < 2; q++) {
        int c = cblk * 64 + (warp << 3) + (q << 2);
        const float* b0 = fm + ((size_t)(bimg * Cc + c)) * (size_t)HW;
        const float* b1 = b0 + HW;
        const float* b2 = b1 + HW;
        const float* b3 = b2 + HW;
        float a0 = 0.f, a1 = 0.f, a2 = 0.f, a3 = 0.f;
        float a4 = 0.f, a5 = 0.f, a6 = 0.f, a7 = 0.f;
        int k = lane;
        for (; k + 32 < n; k += 64) {
            int   o0 = soff[k],  o1 = soff[k + 32];
            float w0 = swt[k],   w1 = swt[k + 32];
            float v0 = b0[o0], v1 = b1[o0], v2 = b2[o0], v3 = b3[o0];
            float v4 = b0[o1], v5 = b1[o1], v6 = b2[o1], v7 = b3[o1];
            a0 += v0 * w0;  a1 += v1 * w0;  a2 += v2 * w0;  a3 += v3 * w0;
            a4 += v4 * w1;  a5 += v5 * w1;  a6 += v6 * w1;  a7 += v7 * w1;
        }
        if (k < n) {
            int o = soff[k]; float w = swt[k];
            a0 += b0[o] * w;  a1 += b1[o] * w;
            a2 += b2[o] * w;  a3 += b3[o] * w;
        }
        float s0 = a0 + a4, s1 = a1 + a5, s2 = a2 + a6, s3 = a3 + a7;
        #pragma unroll
        for (int o = 16; o; o >>= 1) {
            s0 += __shfl_down_sync(0xffffffffu, s0, o);
            s1 += __shfl_down_sync(0xffffffffu, s1, o);
            s2 += __shfl_down_sync(0xffffffffu, s2, o);
            s3 += __shfl_down_sync(0xffffffffu, s3, o);
        }
        if (lane == 0) {
            s0 *= (1.0f / 196.0f);  s1 *= (1.0f / 196.0f);
            s2 *= (1.0f / 196.0f);  s3 *= (1.0f / 196.0f);
            unsigned h0, l0, h1, l1;
            split2(s0, s1, h0, l0);
            split2(s2, s3, h1, l1);
            *reinterpret_cast<uint2*>(&g_Ph[roi][c]) = make_uint2(h0, h1);
            *reinterpret_cast<uint2*>(&g_Pl[roi][c]) = make_uint2(l0, l1);
        }
    }
}

// ---------------- kernel 3: tensor-core GEMM v3 (in-register W split) ----------------
// Block covers full M=144 (3 m-tiles of 48) x 128 n x KSEG=128 k.
// grid (Dd/128=16, KSPLIT=16) = 256 blocks x 384 threads (12 warps = 3m x 4n).
// W is read as fp32 and split to bf16 hi/lo in-register during staging
// (each W element is read exactly once across the grid -> no reuse for a
// precompute pass; this removes the wconv kernel entirely).
#define MMA_BF16(c, a, b0v, b1v)                                             \
    asm volatile("mma.sync.aligned.m16n8k16.row.col.f32.bf16.bf16.f32 "      \
                 "{%0,%1,%2,%3}, {%4,%5,%6,%7}, {%8,%9}, {%0,%1,%2,%3};"     \
                 : "+f"(c[0]), "+f"(c[1]), "+f"(c[2]), "+f"(c[3])            \
                 : "r"(a[0]), "r"(a[1]), "r"(a[2]), "r"(a[3]),               \
                   "r"(b0v), "r"(b1v))

#define LDSM_X4(r, addr)                                                     \
    asm volatile("ldmatrix.sync.aligned.m8n8.x4.shared.b16 {%0,%1,%2,%3}, [%4];" \
                 : "=r"(r[0]), "=r"(r[1]), "=r"(r[2]), "=r"(r[3]) : "r"(addr))

__global__ void __launch_bounds__(384) gemm_kernel(const float* __restrict__ Wm) {
    __shared__ __align__(16) __nv_bfloat16 Ah[144][24], Al[144][24];
    __shared__ __align__(16) __nv_bfloat16 Bh[128][24], Bl[128][24];

    int tid  = threadIdx.x;
    int wid  = tid >> 5, lane = tid & 31;
    int n0   = blockIdx.x * 128;
    int ks   = blockIdx.y;
    int kbase = ks * KSEG;

    int wm = wid % 3;          // warp m-row within 48-tile
    int wn = wid / 3;          // warp n-col (0..3) -> cols wn*32
    int g  = lane >> 3;        // ldmatrix lane group 0..3
    int r  = lane & 7;

    float c[3][4][4] = {};

    for (int it = 0; it < KSEG / 16; it++) {
        int kk = kbase + it * 16;
        // stage: 544 slots; B slots split W fp32 -> bf16 hi/lo in register
        for (int slot = tid; slot < 544; slot += 384) {
            if (slot < 256) {
                int nn = slot >> 1, half = slot & 1;
                const float4* src = reinterpret_cast<const float4*>(
                    Wm + (size_t)(n0 + nn) * Cc + kk + half * 8);
                float4 v0 = src[0], v1 = src[1];
                unsigned h0, l0, h1, l1, h2, l2, h3, l3;
                split2(v0.x, v0.y, h0, l0);
                split2(v0.z, v0.w, h1, l1);
                split2(v1.x, v1.y, h2, l2);
                split2(v1.z, v1.w, h3, l3);
                *reinterpret_cast<uint4*>(&Bh[nn][half * 8]) = make_uint4(h0, h1, h2, h3);
                *reinterpret_cast<uint4*>(&Bl[nn][half * 8]) = make_uint4(l0, l1, l2, l3);
            } else {
                int u = slot - 256, m = u >> 1, half = u & 1;
                *reinterpret_cast<uint4*>(&Ah[m][half * 8]) =
                    *reinterpret_cast<const uint4*>(&g_Ph[m][kk + half * 8]);
                *reinterpret_cast<uint4*>(&Al[m][half * 8]) =
                    *reinterpret_cast<const uint4*>(&g_Pl[m][kk + half * 8]);
            }
        }
        __syncthreads();

        // A fragments: 3 m-tiles, hi+lo, via ldmatrix x4
        unsigned ah3[3][4], al3[3][4];
        #pragma unroll
        for (int mb = 0; mb < 3; mb++) {
            int arow = mb * 48 + wm * 16 + (g & 1) * 8 + r;
            int koff = (g >> 1) * 8;
            unsigned sa_h = (unsigned)__cvta_generic_to_shared(&Ah[arow][koff]);
            unsigned sa_l = (unsigned)__cvta_generic_to_shared(&Al[arow][koff]);
            LDSM_X4(ah3[mb], sa_h);
            LDSM_X4(al3[mb], sa_l);
        }

        // B fragments: 2 pairs of n8-tiles (nf = 2p, 2p+1), hi+lo
        #pragma unroll
        for (int p = 0; p < 2; p++) {
            int brow = wn * 32 + p * 16 + (g >> 1) * 8 + r;
            int koff = (g & 1) * 8;
            unsigned sb_h = (unsigned)__cvta_generic_to_shared(&Bh[brow][koff]);
            unsigned sb_l = (unsigned)__cvta_generic_to_shared(&Bl[brow][koff]);
            unsigned bh[4], bl[4];
            LDSM_X4(bh, sb_h);
            LDSM_X4(bl, sb_l);
            #pragma unroll
            for (int h = 0; h < 2; h++) {
                int nf = 2 * p + h;
                #pragma unroll
                for (int mb = 0; mb < 3; mb++) {
                    MMA_BF16(c[mb][nf], ah3[mb], bh[2*h], bh[2*h+1]);   // hi*hi
                    MMA_BF16(c[mb][nf], ah3[mb], bl[2*h], bl[2*h+1]);   // hi*lo
                    MMA_BF16(c[mb][nf], al3[mb], bh[2*h], bh[2*h+1]);   // lo*hi
                }
            }
        }
        __syncthreads();
    }

    int gq = lane >> 2;        // 0..7 (output row group)
    int tc = lane & 3;
    #pragma unroll
    for (int mb = 0; mb < 3; mb++) {
        int mA = mb * 48 + wm * 16 + gq;
        int mB = mA + 8;
        #pragma unroll
        for (int nf = 0; nf < 4; nf++) {
            int nc = n0 + wn * 32 + nf * 8 + 2 * tc;
            *reinterpret_cast<float2*>(&g_part[ks][mA][nc]) =
                make_float2(c[mb][nf][0], c[mb][nf][1]);
            *reinterpret_cast<float2*>(&g_part[ks][mB][nc]) =
                make_float2(c[mb][nf][2], c[mb][nf][3]);
        }
    }
}

// ---------------- kernel 4: combine partials + bias + mask + permute ----------------
__global__ void combine_kernel(const float* __restrict__ bias,
                               float* __restrict__ out) {
    int m = blockIdx.x;                         // 144
    int n = blockIdx.y * 256 + threadIdx.x;     // 2048
    int bimg = m / TOP;
    float v = 0.0f;
    if (g_valid[m]) {
        v = bias[n];
        #pragma unroll
        for (int s = 0; s < KSPLIT; s++)
            v += g_part[s][m][n];
    }
    out[((size_t)(bimg * TOP + g_dest[m])) * Dd + n] = v;
}

// ---------------- launch ----------------
extern "C" void kernel_launch(void* const* d_in, const int* in_sizes, int n_in,
                              void* d_out, int out_size) {
    const float* boxes  = (const float*)d_in[0];
    const float* scores = (const float*)d_in[1];
    const float* f0     = (const float*)d_in[2];
    const float* f1     = (const float*)d_in[3];
    const float* f2     = (const float*)d_in[4];
    const float* f3     = (const float*)d_in[5];
    const float* Wm     = (const float*)d_in[6];
    const float* bias   = (const float*)d_in[7];
    float* out = (float*)d_out;

    select_kernel<<<Bsz, 128>>>(boxes, scores);
    schedule_kernel<<<1, 160>>>();
    pool_kernel<<<dim3(NROI, 32), 256>>>(f0, f1, f2, f3);
    gemm_kernel<<<dim3(Dd / 128, KSPLIT), 384>>>(Wm);
    combine_kernel<<<dim3(NROI, Dd / 256), 256>>>(bias, out);
}

// round 14
// speedup vs baseline: 1.1933x; 1.1933x over previous
#include <cuda_runtime.h>
#include <cuda_bf16.h>

#define Bsz 4
#define Nn 300
#define TOP 36
#define Cc 2048
#define Dd 2048
#define NROI (Bsz*TOP)
#define KSPLIT 16
#define KSEG (Cc / KSPLIT)   // 128
#define NIT  (KSEG / 16)     // 8

// ---------------- scratch (device globals, no allocation) ----------------
__device__ int   g_valid[NROI];
__device__ int   g_level[NROI];
__device__ int   g_dest[NROI];
__device__ int   g_ny[NROI], g_nx[NROI];
__device__ int   g_yi[NROI][28], g_xi[NROI][28];
__device__ float g_yw[NROI][28], g_xw[NROI][28];
__device__ int   g_order[NROI];
__device__ float g_part[KSPLIT][NROI][Dd];

// bf16 hi/lo decompositions of pooled features (tensor-core GEMM A operand)
__device__ __align__(16) __nv_bfloat16 g_Ph[NROI][Cc];
__device__ __align__(16) __nv_bfloat16 g_Pl[NROI][Cc];

__device__ __forceinline__ int level_size(int l) {
    return (l == 0) ? 100 : (l == 1) ? 50 : (l == 2) ? 25 : 13;
}

// split a,b into bf16 hi + bf16 residual, packed as bf16x2 words
__device__ __forceinline__ void split2(float a, float b, unsigned& h, unsigned& l) {
    __nv_bfloat16 ha = __float2bfloat16(a);
    __nv_bfloat16 hb = __float2bfloat16(b);
    float ra = a - __bfloat162float(ha);
    float rb = b - __bfloat162float(hb);
    __nv_bfloat162 H; H.x = ha; H.y = hb;
    __nv_bfloat162 L; L.x = __float2bfloat16(ra); L.y = __float2bfloat16(rb);
    h = *reinterpret_cast<unsigned*>(&H);
    l = *reinterpret_cast<unsigned*>(&L);
}

// Streaming separable axis table: 14 monotone samples -> merged (idx, weight)
// list (<=28 entries). Exactly replicates reference bilinear accumulation.
__device__ int build_axis(float start, float rlen, int Hs, int* gidx, float* gwt) {
    int   li[28];
    float lw[28];
    int n = 0;
    float step7  = rlen / 7.0f;
    float step14 = rlen / 14.0f;
    for (int i = 0; i < 14; i++) {
        float yy = start + (float)(i >> 1) * step7 + ((float)(i & 1) + 0.5f) * step14;
        if (yy < -1.0f || yy > (float)Hs) continue;
        float yc = fminf(fmaxf(yy, 0.0f), (float)Hs - 1.0f);
        int i0 = (int)floorf(yc);
        int i1 = min(i0 + 1, Hs - 1);
        float w = yc - (float)i0;
        float w0 = 1.0f - w;
        if (n > 0 && li[n-1] == i0)      lw[n-1] += w0;
        else if (n > 1 && li[n-2] == i0) lw[n-2] += w0;
        else { li[n] = i0; lw[n] = w0; n++; }
        if (n > 0 && li[n-1] == i1)      lw[n-1] += w;
        else if (n > 1 && li[n-2] == i1) lw[n-2] += w;
        else { li[n] = i1; lw[n] = w; n++; }
    }
    for (int t = 0; t < n; t++) { gidx[t] = li[t]; gwt[t] = lw[t]; }
    return n;
}

// ---------------- kernel 1: filter + sort + warp NMS + tables + dest ----------------
__global__ void select_kernel(const float* __restrict__ boxes,
                              const float* __restrict__ scores) {
    int b = blockIdx.x;
    int tid = threadIdx.x;
    __shared__ float ss[Nn];
    __shared__ float sx1[Nn], sy1[Nn], sx2[Nn], sy2[Nn];
    __shared__ int   s_selidx[TOP];
    __shared__ int   s_cnt;
    __shared__ int   s_M;
    __shared__ int   keys[TOP];

    const float* sc = scores + b * Nn;
    const float* bx = boxes + (size_t)b * Nn * 4;

    if (tid == 0) s_M = 0;
    for (int i = tid; i < Nn; i += blockDim.x) ss[i] = sc[i];
    __syncthreads();

    {
        int local = 0;
        for (int i = tid; i < Nn; i += blockDim.x) local += (ss[i] > 0.3f);
        #pragma unroll
        for (int o = 16; o; o >>= 1) local += __shfl_down_sync(0xffffffffu, local, o);
        if ((tid & 31) == 0 && local) atomicAdd(&s_M, local);
    }

    for (int i = tid; i < Nn; i += blockDim.x) {
        float si = ss[i];
        if (si > 0.3f) {
            int rank = 0;
            for (int j = 0; j < Nn; j++) {
                float sj = ss[j];
                rank += (sj > 0.3f) && ((sj > si) || (sj == si && j < i));
            }
            sx1[rank] = bx[i * 4 + 0];
            sy1[rank] = bx[i * 4 + 1];
            sx2[rank] = bx[i * 4 + 2];
            sy2[rank] = bx[i * 4 + 3];
        }
    }
    __syncthreads();

    int M = s_M;

    if (tid < 32) {
        int lane = tid;
        unsigned kmask = 0;
        #pragma unroll
        for (int s2 = 0; s2 < 10; s2++)
            if (lane + 32 * s2 < M) kmask |= (1u << s2);
        int cnt = 0;
        for (int i = 0; i < M; i++) {
            unsigned om = __shfl_sync(0xffffffffu, kmask, i & 31);
            if (!((om >> (i >> 5)) & 1u)) continue;
            if (lane == 0) s_selidx[cnt] = i;
            cnt++;
            if (cnt >= TOP) break;
            float x1 = sx1[i], y1 = sy1[i], x2 = sx2[i], y2 = sy2[i];
            float ai = (x2 - x1) * (y2 - y1);
            #pragma unroll
            for (int s2 = 0; s2 < 10; s2++) {
                int j = lane + 32 * s2;
                if (((kmask >> s2) & 1u) && j > i && j < M) {
                    float jx1 = sx1[j], jy1 = sy1[j], jx2 = sx2[j], jy2 = sy2[j];
                    float xx1 = fmaxf(x1, jx1);
                    float yy1 = fmaxf(y1, jy1);
                    float xx2 = fminf(x2, jx2);
                    float yy2 = fminf(y2, jy2);
                    float inter = fmaxf(xx2 - xx1, 0.0f) * fmaxf(yy2 - yy1, 0.0f);
                    float aj = (jx2 - jx1) * (jy2 - jy1);
                    float iou = inter / (ai + aj - inter);
                    if (iou > 0.7f) kmask &= ~(1u << s2);
                }
            }
        }
        if (lane == 0) s_cnt = cnt;
    }
    __syncthreads();

    if (tid < TOP) {
        int r = tid;
        int roi = b * TOP + r;
        int valid = 0, lvl = 0;
        if (r < s_cnt) {
            valid = 1;
            int i = s_selidx[r];
            float bx0 = sx1[i], bx1 = sy1[i], bx2 = sx2[i], bx3 = sy2[i];
            float dx = bx2 - bx0, dy = bx3 - bx1;
            float diag = sqrtf(dx * dx + dy * dy);
            float lf = floorf(4.0f + log2f(diag / 224.0f * 4.0f));
            lf = fminf(fmaxf(lf, 2.0f), 5.0f);
            lvl = (int)lf - 2;
            int Hs = level_size(lvl);
            float rw = fmaxf(bx2 - bx0, 1.0f);
            float rh = fmaxf(bx3 - bx1, 1.0f);
            g_ny[roi] = build_axis(bx1, rh, Hs, g_yi[roi], g_yw[roi]);
            g_nx[roi] = build_axis(bx0, rw, Hs, g_xi[roi], g_xw[roi]);
        } else {
            g_ny[roi] = 0;
            g_nx[roi] = 0;
        }
        g_valid[roi] = valid;
        g_level[roi] = lvl;
        keys[r] = valid ? (lvl * TOP + r) : (4 * TOP + r);
    }
    __syncthreads();
    if (tid < TOP) {
        int k = keys[tid];
        int d = 0;
        for (int q = 0; q < TOP; q++) d += (keys[q] < k);
        g_dest[b * TOP + tid] = d;
    }
}

// ---------------- kernel 1b: LPT ordering (slow level-0 rois first) ----------------
__global__ void schedule_kernel() {
    __shared__ int keys[NROI];
    int t = threadIdx.x;
    if (t < NROI) {
        int lvl = g_level[t];
        int img = t / TOP;
        keys[t] = g_valid[t] ? (lvl * 8 + img) : 1024;
    }
    __syncthreads();
    if (t < NROI) {
        int k = keys[t];
        int rank = 0;
        for (int j = 0; j < NROI; j++)
            rank += (keys[j] < k) || (keys[j] == k && j < t);
        g_order[rank] = t;
    }
}

// ---------------- kernel 2: ROI pooling (R6 tap-gather + inline bf16 hi/lo epilogue) ----------------
__global__ void pool_kernel(const float* __restrict__ f0, const float* __restrict__ f1,
                            const float* __restrict__ f2, const float* __restrict__ f3) {
    int roi  = g_order[blockIdx.x];
    int cblk = blockIdx.y;
    int tid  = threadIdx.x;

    if (!g_valid[roi]) {
        if (tid < 64) {
            int c = cblk * 64 + tid;
            g_Ph[roi][c] = __float2bfloat16(0.0f);
            g_Pl[roi][c] = __float2bfloat16(0.0f);
        }
        return;
    }

    __shared__ int   soff[784];
    __shared__ float swt[784];

    int lvl = g_level[roi];
    int Hs  = level_size(lvl);
    int HW  = Hs * Hs;
    const float* fm = (lvl == 0) ? f0 : (lvl == 1) ? f1 : (lvl == 2) ? f2 : f3;

    int ny = g_ny[roi], nx = g_nx[roi];
    int n = ny * nx;
    for (int k = tid; k < n; k += 256) {
        int a = k / nx;
        int q = k - a * nx;
        soff[k] = g_yi[roi][a] * Hs + g_xi[roi][q];
        swt[k]  = g_yw[roi][a] * g_xw[roi][q];
    }
    __syncthreads();

    int bimg = roi / TOP;
    int warp = tid >> 5, lane = tid & 31;
    #pragma unroll
    for (int q = 0; q < 2; q++) {
        int c = cblk * 64 + (warp << 3) + (q << 2);
        const float* b0 = fm + ((size_t)(bimg * Cc + c)) * (size_t)HW;
        const float* b1 = b0 + HW;
        const float* b2 = b1 + HW;
        const float* b3 = b2 + HW;
        float a0 = 0.f, a1 = 0.f, a2 = 0.f, a3 = 0.f;
        float a4 = 0.f, a5 = 0.f, a6 = 0.f, a7 = 0.f;
        int k = lane;
        for (; k + 32 < n; k += 64) {
            int   o0 = soff[k],  o1 = soff[k + 32];
            float w0 = swt[k],   w1 = swt[k + 32];
            float v0 = b0[o0], v1 = b1[o0], v2 = b2[o0], v3 = b3[o0];
            float v4 = b0[o1], v5 = b1[o1], v6 = b2[o1], v7 = b3[o1];
            a0 += v0 * w0;  a1 += v1 * w0;  a2 += v2 * w0;  a3 += v3 * w0;
            a4 += v4 * w1;  a5 += v5 * w1;  a6 += v6 * w1;  a7 += v7 * w1;
        }
        if (k < n) {
            int o = soff[k]; float w = swt[k];
            a0 += b0[o] * w;  a1 += b1[o] * w;
            a2 += b2[o] * w;  a3 += b3[o] * w;
        }
        float s0 = a0 + a4, s1 = a1 + a5, s2 = a2 + a6, s3 = a3 + a7;
        #pragma unroll
        for (int o = 16; o; o >>= 1) {
            s0 += __shfl_down_sync(0xffffffffu, s0, o);
            s1 += __shfl_down_sync(0xffffffffu, s1, o);
            s2 += __shfl_down_sync(0xffffffffu, s2, o);
            s3 += __shfl_down_sync(0xffffffffu, s3, o);
        }
        if (lane == 0) {
            s0 *= (1.0f / 196.0f);  s1 *= (1.0f / 196.0f);
            s2 *= (1.0f / 196.0f);  s3 *= (1.0f / 196.0f);
            unsigned h0, l0, h1, l1;
            split2(s0, s1, h0, l0);
            split2(s2, s3, h1, l1);
            *reinterpret_cast<uint2*>(&g_Ph[roi][c]) = make_uint2(h0, h1);
            *reinterpret_cast<uint2*>(&g_Pl[roi][c]) = make_uint2(l0, l1);
        }
    }
}

// ---------------- kernel 3: tensor-core GEMM v4 (double-buffered staging) ----------------
// Block covers full M=144 (3 m-tiles of 48) x 128 n x KSEG=128 k.
// grid (Dd/128=16, KSPLIT=16) = 256 blocks x 384 threads (12 warps = 3m x 4n).
// Fixed per-thread staging slots; global loads for iteration it+1 are issued
// before computing iteration it (register prefetch), so the LDG + fp32->bf16
// split chain overlaps the MMA work. Two smem buffers (dynamic, 52KB).
#define MMA_BF16(c, a, b0v, b1v)                                             \
    asm volatile("mma.sync.aligned.m16n8k16.row.col.f32.bf16.bf16.f32 "      \
                 "{%0,%1,%2,%3}, {%4,%5,%6,%7}, {%8,%9}, {%0,%1,%2,%3};"     \
                 : "+f"(c[0]), "+f"(c[1]), "+f"(c[2]), "+f"(c[3])            \
                 : "r"(a[0]), "r"(a[1]), "r"(a[2]), "r"(a[3]),               \
                   "r"(b0v), "r"(b1v))

#define LDSM_X4(r, addr)                                                     \
    asm volatile("ldmatrix.sync.aligned.m8n8.x4.shared.b16 {%0,%1,%2,%3}, [%4];" \
                 : "=r"(r[0]), "=r"(r[1]), "=r"(r[2]), "=r"(r[3]) : "r"(addr))

// dynamic smem element offsets (bf16 units)
#define G_AH 0
#define G_AL (G_AH + 2 * 144 * 24)
#define G_BH (G_AL + 2 * 144 * 24)
#define G_BL (G_BH + 2 * 128 * 24)
#define GEMM_SMEM_ELEMS (G_BL + 2 * 128 * 24)
#define GEMM_SMEM_BYTES (GEMM_SMEM_ELEMS * 2)

__global__ void __launch_bounds__(384) gemm_kernel(const float* __restrict__ Wm) {
    extern __shared__ __nv_bfloat16 smg[];
    __nv_bfloat16* sAh = smg + G_AH;
    __nv_bfloat16* sAl = smg + G_AL;
    __nv_bfloat16* sBh = smg + G_BH;
    __nv_bfloat16* sBl = smg + G_BL;

    int tid  = threadIdx.x;
    int wid  = tid >> 5, lane = tid & 31;
    int n0   = blockIdx.x * 128;
    int ks   = blockIdx.y;
    int kbase = ks * KSEG;

    int wm = wid % 3;
    int wn = wid / 3;
    int g  = lane >> 3;
    int r  = lane & 7;

    // fixed staging slots
    bool hasB = (tid < 256);
    int  bnn = tid >> 1, bhalf = tid & 1;              // B slot (tid<256)
    bool hasA = (tid >= 256) || (tid < 160);
    int  au = (tid >= 256) ? (tid - 256) : (tid + 128); // A slot id 0..287
    int  am = au >> 1, ahalf = au & 1;

    const float4* wsrc = hasB
        ? reinterpret_cast<const float4*>(Wm + (size_t)(n0 + bnn) * Cc + kbase + bhalf * 8)
        : nullptr;

    float4 bw0, bw1;
    uint4  par_h, par_l;

    // ---- load regs for iteration `it` ----
    #define LOAD_REGS(it)                                                        \
        do {                                                                     \
            if (hasB) { bw0 = wsrc[(it) * 4]; bw1 = wsrc[(it) * 4 + 1]; }        \
            if (hasA) {                                                          \
                par_h = *reinterpret_cast<const uint4*>(                         \
                    &g_Ph[am][kbase + (it) * 16 + ahalf * 8]);                   \
                par_l = *reinterpret_cast<const uint4*>(                         \
                    &g_Pl[am][kbase + (it) * 16 + ahalf * 8]);                   \
            }                                                                    \
        } while (0)

    // ---- store regs to buffer `nb` ----
    #define STORE_REGS(nb)                                                       \
        do {                                                                     \
            if (hasB) {                                                          \
                unsigned h0, l0, h1, l1, h2, l2, h3, l3;                         \
                split2(bw0.x, bw0.y, h0, l0);                                    \
                split2(bw0.z, bw0.w, h1, l1);                                    \
                split2(bw1.x, bw1.y, h2, l2);                                    \
                split2(bw1.z, bw1.w, h3, l3);                                    \
                *reinterpret_cast<uint4*>(&sBh[(nb) * 3072 + bnn * 24 + bhalf * 8]) \
                    = make_uint4(h0, h1, h2, h3);                                \
                *reinterpret_cast<uint4*>(&sBl[(nb) * 3072 + bnn * 24 + bhalf * 8]) \
                    = make_uint4(l0, l1, l2, l3);                                \
            }                                                                    \
            if (hasA) {                                                          \
                *reinterpret_cast<uint4*>(&sAh[(nb) * 3456 + am * 24 + ahalf * 8]) = par_h; \
                *reinterpret_cast<uint4*>(&sAl[(nb) * 3456 + am * 24 + ahalf * 8]) = par_l; \
            }                                                                    \
        } while (0)

    float c[3][4][4] = {};

    LOAD_REGS(0);
    STORE_REGS(0);
    __syncthreads();

    for (int it = 0; it < NIT; it++) {
        int buf = it & 1;
        if (it + 1 < NIT) LOAD_REGS(it + 1);

        const __nv_bfloat16* bAh = sAh + buf * 3456;
        const __nv_bfloat16* bAl = sAl + buf * 3456;
        const __nv_bfloat16* bBh = sBh + buf * 3072;
        const __nv_bfloat16* bBl = sBl + buf * 3072;

        unsigned ah3[3][4], al3[3][4];
        #pragma unroll
        for (int mb = 0; mb < 3; mb++) {
            int arow = mb * 48 + wm * 16 + (g & 1) * 8 + r;
            int koff = (g >> 1) * 8;
            unsigned sa_h = (unsigned)__cvta_generic_to_shared(&bAh[arow * 24 + koff]);
            unsigned sa_l = (unsigned)__cvta_generic_to_shared(&bAl[arow * 24 + koff]);
            LDSM_X4(ah3[mb], sa_h);
            LDSM_X4(al3[mb], sa_l);
        }

        #pragma unroll
        for (int p = 0; p < 2; p++) {
            int brow = wn * 32 + p * 16 + (g >> 1) * 8 + r;
            int koff = (g & 1) * 8;
            unsigned sb_h = (unsigned)__cvta_generic_to_shared(&bBh[brow * 24 + koff]);
            unsigned sb_l = (unsigned)__cvta_generic_to_shared(&bBl[brow * 24 + koff]);
            unsigned bh[4], bl[4];
            LDSM_X4(bh, sb_h);
            LDSM_X4(bl, sb_l);
            #pragma unroll
            for (int h = 0; h < 2; h++) {
                int nf = 2 * p + h;
                #pragma unroll
                for (int mb = 0; mb < 3; mb++) {
                    MMA_BF16(c[mb][nf], ah3[mb], bh[2*h], bh[2*h+1]);   // hi*hi
                    MMA_BF16(c[mb][nf], ah3[mb], bl[2*h], bl[2*h+1]);   // hi*lo
                    MMA_BF16(c[mb][nf], al3[mb], bh[2*h], bh[2*h+1]);   // lo*hi
                }
            }
        }
        __syncthreads();
        if (it + 1 < NIT) {
            STORE_REGS(buf ^ 1);
            __syncthreads();
        }
    }

    int gq = lane >> 2;
    int tc = lane & 3;
    #pragma unroll
    for (int mb = 0; mb < 3; mb++) {
        int mA = mb * 48 + wm * 16 + gq;
        int mB = mA + 8;
        #pragma unroll
        for (int nf = 0; nf < 4; nf++) {
            int nc = n0 + wn * 32 + nf * 8 + 2 * tc;
            *reinterpret_cast<float2*>(&g_part[ks][mA][nc]) =
                make_float2(c[mb][nf][0], c[mb][nf][1]);
            *reinterpret_cast<float2*>(&g_part[ks][mB][nc]) =
                make_float2(c[mb][nf][2], c[mb][nf][3]);
        }
    }
}

// ---------------- kernel 4: combine partials + bias + mask + permute ----------------
__global__ void combine_kernel(const float* __restrict__ bias,
                               float* __restrict__ out) {
    int m = blockIdx.x;                         // 144
    int n = blockIdx.y * 256 + threadIdx.x;     // 2048
    int bimg = m / TOP;
    float v = 0.0f;
    if (g_valid[m]) {
        v = bias[n];
        #pragma unroll
        for (int s = 0; s < KSPLIT; s++)
            v += g_part[s][m][n];
    }
    out[((size_t)(bimg * TOP + g_dest[m])) * Dd + n] = v;
}

// ---------------- launch ----------------
extern "C" void kernel_launch(void* const* d_in, const int* in_sizes, int n_in,
                              void* d_out, int out_size) {
    const float* boxes  = (const float*)d_in[0];
    const float* scores = (const float*)d_in[1];
    const float* f0     = (const float*)d_in[2];
    const float* f1     = (const float*)d_in[3];
    const float* f2     = (const float*)d_in[4];
    const float* f3     = (const float*)d_in[5];
    const float* Wm     = (const float*)d_in[6];
    const float* bias   = (const float*)d_in[7];
    float* out = (float*)d_out;

    cudaFuncSetAttribute(gemm_kernel,
                         cudaFuncAttributeMaxDynamicSharedMemorySize,
                         GEMM_SMEM_BYTES);

    select_kernel<<<Bsz, 320>>>(boxes, scores);
    schedule_kernel<<<1, 160>>>();
    pool_kernel<<<dim3(NROI, 32), 256>>>(f0, f1, f2, f3);
    gemm_kernel<<<dim3(Dd / 128, KSPLIT), 384, GEMM_SMEM_BYTES>>>(Wm);
    combine_kernel<<<dim3(NROI, Dd / 256), 256>>>(bias, out);
}

// round 15
// speedup vs baseline: 1.2013x; 1.0067x over previous
#include <cuda_runtime.h>
#include <cuda_bf16.h>

#define Bsz 4
#define Nn 300
#define TOP 36
#define Cc 2048
#define Dd 2048
#define NROI (Bsz*TOP)
#define KSPLIT 16
#define KSEG (Cc / KSPLIT)   // 128
#define NIT  (KSEG / 16)     // 8

// ---------------- scratch (device globals, no allocation) ----------------
__device__ int   g_valid[NROI];
__device__ int   g_level[NROI];
__device__ int   g_dest[NROI];
__device__ int   g_ny[NROI], g_nx[NROI];
__device__ int   g_yi[NROI][28], g_xi[NROI][28];
__device__ float g_yw[NROI][28], g_xw[NROI][28];
__device__ int   g_order[NROI];
__device__ float g_part[KSPLIT][NROI][Dd];

// bf16 hi/lo decompositions of pooled features (tensor-core GEMM A operand)
__device__ __align__(16) __nv_bfloat16 g_Ph[NROI][Cc];
__device__ __align__(16) __nv_bfloat16 g_Pl[NROI][Cc];

__device__ __forceinline__ int level_size(int l) {
    return (l == 0) ? 100 : (l == 1) ? 50 : (l == 2) ? 25 : 13;
}

// split a,b into bf16 hi + bf16 residual, packed as bf16x2 words
__device__ __forceinline__ void split2(float a, float b, unsigned& h, unsigned& l) {
    __nv_bfloat16 ha = __float2bfloat16(a);
    __nv_bfloat16 hb = __float2bfloat16(b);
    float ra = a - __bfloat162float(ha);
    float rb = b - __bfloat162float(hb);
    __nv_bfloat162 H; H.x = ha; H.y = hb;
    __nv_bfloat162 L; L.x = __float2bfloat16(ra); L.y = __float2bfloat16(rb);
    h = *reinterpret_cast<unsigned*>(&H);
    l = *reinterpret_cast<unsigned*>(&L);
}

// Streaming separable axis table: 14 monotone samples -> merged (idx, weight)
// list (<=28 entries). Exactly replicates reference bilinear accumulation.
__device__ int build_axis(float start, float rlen, int Hs, int* gidx, float* gwt) {
    int   li[28];
    float lw[28];
    int n = 0;
    float step7  = rlen / 7.0f;
    float step14 = rlen / 14.0f;
    for (int i = 0; i < 14; i++) {
        float yy = start + (float)(i >> 1) * step7 + ((float)(i & 1) + 0.5f) * step14;
        if (yy < -1.0f || yy > (float)Hs) continue;
        float yc = fminf(fmaxf(yy, 0.0f), (float)Hs - 1.0f);
        int i0 = (int)floorf(yc);
        int i1 = min(i0 + 1, Hs - 1);
        float w = yc - (float)i0;
        float w0 = 1.0f - w;
        if (n > 0 && li[n-1] == i0)      lw[n-1] += w0;
        else if (n > 1 && li[n-2] == i0) lw[n-2] += w0;
        else { li[n] = i0; lw[n] = w0; n++; }
        if (n > 0 && li[n-1] == i1)      lw[n-1] += w;
        else if (n > 1 && li[n-2] == i1) lw[n-2] += w;
        else { li[n] = i1; lw[n] = w; n++; }
    }
    for (int t = 0; t < n; t++) { gidx[t] = li[t]; gwt[t] = lw[t]; }
    return n;
}

// ---------------- kernel 1: filter + sort + warp NMS + tables + dest ----------------
__global__ void select_kernel(const float* __restrict__ boxes,
                              const float* __restrict__ scores) {
    int b = blockIdx.x;
    int tid = threadIdx.x;
    __shared__ float ss[Nn];
    __shared__ float sx1[Nn], sy1[Nn], sx2[Nn], sy2[Nn];
    __shared__ int   s_selidx[TOP];
    __shared__ int   s_cnt;
    __shared__ int   s_M;
    __shared__ int   keys[TOP];

    const float* sc = scores + b * Nn;
    const float* bx = boxes + (size_t)b * Nn * 4;

    if (tid == 0) s_M = 0;
    for (int i = tid; i < Nn; i += blockDim.x) ss[i] = sc[i];
    __syncthreads();

    {
        int local = 0;
        for (int i = tid; i < Nn; i += blockDim.x) local += (ss[i] > 0.3f);
        #pragma unroll
        for (int o = 16; o; o >>= 1) local += __shfl_down_sync(0xffffffffu, local, o);
        if ((tid & 31) == 0 && local) atomicAdd(&s_M, local);
    }

    for (int i = tid; i < Nn; i += blockDim.x) {
        float si = ss[i];
        if (si > 0.3f) {
            int rank = 0;
            for (int j = 0; j < Nn; j++) {
                float sj = ss[j];
                rank += (sj > 0.3f) && ((sj > si) || (sj == si && j < i));
            }
            sx1[rank] = bx[i * 4 + 0];
            sy1[rank] = bx[i * 4 + 1];
            sx2[rank] = bx[i * 4 + 2];
            sy2[rank] = bx[i * 4 + 3];
        }
    }
    __syncthreads();

    int M = s_M;

    if (tid < 32) {
        int lane = tid;
        unsigned kmask = 0;
        #pragma unroll
        for (int s2 = 0; s2 < 10; s2++)
            if (lane + 32 * s2 < M) kmask |= (1u << s2);
        int cnt = 0;
        for (int i = 0; i < M; i++) {
            unsigned om = __shfl_sync(0xffffffffu, kmask, i & 31);
            if (!((om >> (i >> 5)) & 1u)) continue;
            if (lane == 0) s_selidx[cnt] = i;
            cnt++;
            if (cnt >= TOP) break;
            float x1 = sx1[i], y1 = sy1[i], x2 = sx2[i], y2 = sy2[i];
            float ai = (x2 - x1) * (y2 - y1);
            #pragma unroll
            for (int s2 = 0; s2 < 10; s2++) {
                int j = lane + 32 * s2;
                if (((kmask >> s2) & 1u) && j > i && j < M) {
                    float jx1 = sx1[j], jy1 = sy1[j], jx2 = sx2[j], jy2 = sy2[j];
                    float xx1 = fmaxf(x1, jx1);
                    float yy1 = fmaxf(y1, jy1);
                    float xx2 = fminf(x2, jx2);
                    float yy2 = fminf(y2, jy2);
                    float inter = fmaxf(xx2 - xx1, 0.0f) * fmaxf(yy2 - yy1, 0.0f);
                    float aj = (jx2 - jx1) * (jy2 - jy1);
                    float iou = inter / (ai + aj - inter);
                    if (iou > 0.7f) kmask &= ~(1u << s2);
                }
            }
        }
        if (lane == 0) s_cnt = cnt;
    }
    __syncthreads();

    if (tid < TOP) {
        int r = tid;
        int roi = b * TOP + r;
        int valid = 0, lvl = 0;
        if (r < s_cnt) {
            valid = 1;
            int i = s_selidx[r];
            float bx0 = sx1[i], bx1 = sy1[i], bx2 = sx2[i], bx3 = sy2[i];
            float dx = bx2 - bx0, dy = bx3 - bx1;
            float diag = sqrtf(dx * dx + dy * dy);
            float lf = floorf(4.0f + log2f(diag / 224.0f * 4.0f));
            lf = fminf(fmaxf(lf, 2.0f), 5.0f);
            lvl = (int)lf - 2;
            int Hs = level_size(lvl);
            float rw = fmaxf(bx2 - bx0, 1.0f);
            float rh = fmaxf(bx3 - bx1, 1.0f);
            g_ny[roi] = build_axis(bx1, rh, Hs, g_yi[roi], g_yw[roi]);
            g_nx[roi] = build_axis(bx0, rw, Hs, g_xi[roi], g_xw[roi]);
        } else {
            g_ny[roi] = 0;
            g_nx[roi] = 0;
        }
        g_valid[roi] = valid;
        g_level[roi] = lvl;
        keys[r] = valid ? (lvl * TOP + r) : (4 * TOP + r);
    }
    __syncthreads();
    if (tid < TOP) {
        int k = keys[tid];
        int d = 0;
        for (int q = 0; q < TOP; q++) d += (keys[q] < k);
        g_dest[b * TOP + tid] = d;
    }
}

// ---------------- kernel 1b: LPT ordering (slow level-0 rois first) ----------------
__global__ void schedule_kernel() {
    __shared__ int keys[NROI];
    int t = threadIdx.x;
    if (t < NROI) {
        int lvl = g_level[t];
        int img = t / TOP;
        keys[t] = g_valid[t] ? (lvl * 8 + img) : 1024;
    }
    __syncthreads();
    if (t < NROI) {
        int k = keys[t];
        int rank = 0;
        for (int j = 0; j < NROI; j++)
            rank += (keys[j] < k) || (keys[j] == k && j < t);
        g_order[rank] = t;
    }
}

// ---------------- kernel 2: ROI pooling (R6 tap-gather + inline bf16 hi/lo epilogue) ----------------
__global__ void pool_kernel(const float* __restrict__ f0, const float* __restrict__ f1,
                            const float* __restrict__ f2, const float* __restrict__ f3) {
    int roi  = g_order[blockIdx.x];
    int cblk = blockIdx.y;
    int tid  = threadIdx.x;

    if (!g_valid[roi]) {
        if (tid < 64) {
            int c = cblk * 64 + tid;
            g_Ph[roi][c] = __float2bfloat16(0.0f);
            g_Pl[roi][c] = __float2bfloat16(0.0f);
        }
        return;
    }

    __shared__ int   soff[784];
    __shared__ float swt[784];

    int lvl = g_level[roi];
    int Hs  = level_size(lvl);
    int HW  = Hs * Hs;
    const float* fm = (lvl == 0) ? f0 : (lvl == 1) ? f1 : (lvl == 2) ? f2 : f3;

    int ny = g_ny[roi], nx = g_nx[roi];
    int n = ny * nx;
    for (int k = tid; k < n; k += 256) {
        int a = k / nx;
        int q = k - a * nx;
        soff[k] = g_yi[roi][a] * Hs + g_xi[roi][q];
        swt[k]  = g_yw[roi][a] * g_xw[roi][q];
    }
    __syncthreads();

    int bimg = roi / TOP;
    int warp = tid >> 5, lane = tid & 31;
    #pragma unroll
    for (int q = 0; q < 2; q++) {
        int c = cblk * 64 + (warp << 3) + (q << 2);
        const float* b0 = fm + ((size_t)(bimg * Cc + c)) * (size_t)HW;
        const float* b1 = b0 + HW;
        const float* b2 = b1 + HW;
        const float* b3 = b2 + HW;
        float a0 = 0.f, a1 = 0.f, a2 = 0.f, a3 = 0.f;
        float a4 = 0.f, a5 = 0.f, a6 = 0.f, a7 = 0.f;
        int k = lane;
        for (; k + 32 < n; k += 64) {
            int   o0 = soff[k],  o1 = soff[k + 32];
            float w0 = swt[k],   w1 = swt[k + 32];
            float v0 = b0[o0], v1 = b1[o0], v2 = b2[o0], v3 = b3[o0];
            float v4 = b0[o1], v5 = b1[o1], v6 = b2[o1], v7 = b3[o1];
            a0 += v0 * w0;  a1 += v1 * w0;  a2 += v2 * w0;  a3 += v3 * w0;
            a4 += v4 * w1;  a5 += v5 * w1;  a6 += v6 * w1;  a7 += v7 * w1;
        }
        if (k < n) {
            int o = soff[k]; float w = swt[k];
            a0 += b0[o] * w;  a1 += b1[o] * w;
            a2 += b2[o] * w;  a3 += b3[o] * w;
        }
        float s0 = a0 + a4, s1 = a1 + a5, s2 = a2 + a6, s3 = a3 + a7;
        #pragma unroll
        for (int o = 16; o; o >>= 1) {
            s0 += __shfl_down_sync(0xffffffffu, s0, o);
            s1 += __shfl_down_sync(0xffffffffu, s1, o);
            s2 += __shfl_down_sync(0xffffffffu, s2, o);
            s3 += __shfl_down_sync(0xffffffffu, s3, o);
        }
        if (lane == 0) {
            s0 *= (1.0f / 196.0f);  s1 *= (1.0f / 196.0f);
            s2 *= (1.0f / 196.0f);  s3 *= (1.0f / 196.0f);
            unsigned h0, l0, h1, l1;
            split2(s0, s1, h0, l0);
            split2(s2, s3, h1, l1);
            *reinterpret_cast<uint2*>(&g_Ph[roi][c]) = make_uint2(h0, h1);
            *reinterpret_cast<uint2*>(&g_Pl[roi][c]) = make_uint2(l0, l1);
        }
    }
}

// ---------------- kernel 3: tensor-core GEMM v5 (double-buffer, single sync/iter) ----------------
// Block covers full M=144 (3 m-tiles of 48) x 128 n x KSEG=128 k.
// grid (Dd/128=16, KSPLIT=16) = 256 blocks x 384 threads (12 warps = 3m x 4n).
// One __syncthreads per k-iteration: compute reads buf while STORE writes
// buf^1 (disjoint); buf^1's previous readers all passed the prior barrier.
#define MMA_BF16(c, a, b0v, b1v)                                             \
    asm volatile("mma.sync.aligned.m16n8k16.row.col.f32.bf16.bf16.f32 "      \
                 "{%0,%1,%2,%3}, {%4,%5,%6,%7}, {%8,%9}, {%0,%1,%2,%3};"     \
                 : "+f"(c[0]), "+f"(c[1]), "+f"(c[2]), "+f"(c[3])            \
                 : "r"(a[0]), "r"(a[1]), "r"(a[2]), "r"(a[3]),               \
                   "r"(b0v), "r"(b1v))

#define LDSM_X4(r, addr)                                                     \
    asm volatile("ldmatrix.sync.aligned.m8n8.x4.shared.b16 {%0,%1,%2,%3}, [%4];" \
                 : "=r"(r[0]), "=r"(r[1]), "=r"(r[2]), "=r"(r[3]) : "r"(addr))

// dynamic smem element offsets (bf16 units)
#define G_AH 0
#define G_AL (G_AH + 2 * 144 * 24)
#define G_BH (G_AL + 2 * 144 * 24)
#define G_BL (G_BH + 2 * 128 * 24)
#define GEMM_SMEM_ELEMS (G_BL + 2 * 128 * 24)
#define GEMM_SMEM_BYTES (GEMM_SMEM_ELEMS * 2)

__global__ void __launch_bounds__(384) gemm_kernel(const float* __restrict__ Wm) {
    extern __shared__ __nv_bfloat16 smg[];
    __nv_bfloat16* sAh = smg + G_AH;
    __nv_bfloat16* sAl = smg + G_AL;
    __nv_bfloat16* sBh = smg + G_BH;
    __nv_bfloat16* sBl = smg + G_BL;

    int tid  = threadIdx.x;
    int wid  = tid >> 5, lane = tid & 31;
    int n0   = blockIdx.x * 128;
    int ks   = blockIdx.y;
    int kbase = ks * KSEG;

    int wm = wid % 3;
    int wn = wid / 3;
    int g  = lane >> 3;
    int r  = lane & 7;

    // fixed staging slots
    bool hasB = (tid < 256);
    int  bnn = tid >> 1, bhalf = tid & 1;              // B slot (tid<256)
    bool hasA = (tid >= 256) || (tid < 160);
    int  au = (tid >= 256) ? (tid - 256) : (tid + 128); // A slot id 0..287
    int  am = au >> 1, ahalf = au & 1;

    const float4* wsrc = hasB
        ? reinterpret_cast<const float4*>(Wm + (size_t)(n0 + bnn) * Cc + kbase + bhalf * 8)
        : nullptr;

    float4 bw0, bw1;
    uint4  par_h, par_l;

    #define LOAD_REGS(it)                                                        \
        do {                                                                     \
            if (hasB) { bw0 = wsrc[(it) * 4]; bw1 = wsrc[(it) * 4 + 1]; }        \
            if (hasA) {                                                          \
                par_h = *reinterpret_cast<const uint4*>(                         \
                    &g_Ph[am][kbase + (it) * 16 + ahalf * 8]);                   \
                par_l = *reinterpret_cast<const uint4*>(                         \
                    &g_Pl[am][kbase + (it) * 16 + ahalf * 8]);                   \
            }                                                                    \
        } while (0)

    #define STORE_REGS(nb)                                                       \
        do {                                                                     \
            if (hasB) {                                                          \
                unsigned h0, l0, h1, l1, h2, l2, h3, l3;                         \
                split2(bw0.x, bw0.y, h0, l0);                                    \
                split2(bw0.z, bw0.w, h1, l1);                                    \
                split2(bw1.x, bw1.y, h2, l2);                                    \
                split2(bw1.z, bw1.w, h3, l3);                                    \
                *reinterpret_cast<uint4*>(&sBh[(nb) * 3072 + bnn * 24 + bhalf * 8]) \
                    = make_uint4(h0, h1, h2, h3);                                \
                *reinterpret_cast<uint4*>(&sBl[(nb) * 3072 + bnn * 24 + bhalf * 8]) \
                    = make_uint4(l0, l1, l2, l3);                                \
            }                                                                    \
            if (hasA) {                                                          \
                *reinterpret_cast<uint4*>(&sAh[(nb) * 3456 + am * 24 + ahalf * 8]) = par_h; \
                *reinterpret_cast<uint4*>(&sAl[(nb) * 3456 + am * 24 + ahalf * 8]) = par_l; \
            }                                                                    \
        } while (0)

    float c[3][4][4] = {};

    LOAD_REGS(0);
    STORE_REGS(0);
    __syncthreads();

    for (int it = 0; it < NIT; it++) {
        int buf = it & 1;
        if (it + 1 < NIT) LOAD_REGS(it + 1);

        const __nv_bfloat16* bAh = sAh + buf * 3456;
        const __nv_bfloat16* bAl = sAl + buf * 3456;
        const __nv_bfloat16* bBh = sBh + buf * 3072;
        const __nv_bfloat16* bBl = sBl + buf * 3072;

        unsigned ah3[3][4], al3[3][4];
        #pragma unroll
        for (int mb = 0; mb < 3; mb++) {
            int arow = mb * 48 + wm * 16 + (g & 1) * 8 + r;
            int koff = (g >> 1) * 8;
            unsigned sa_h = (unsigned)__cvta_generic_to_shared(&bAh[arow * 24 + koff]);
            unsigned sa_l = (unsigned)__cvta_generic_to_shared(&bAl[arow * 24 + koff]);
            LDSM_X4(ah3[mb], sa_h);
            LDSM_X4(al3[mb], sa_l);
        }

        #pragma unroll
        for (int p = 0; p < 2; p++) {
            int brow = wn * 32 + p * 16 + (g >> 1) * 8 + r;
            int koff = (g & 1) * 8;
            unsigned sb_h = (unsigned)__cvta_generic_to_shared(&bBh[brow * 24 + koff]);
            unsigned sb_l = (unsigned)__cvta_generic_to_shared(&bBl[brow * 24 + koff]);
            unsigned bh[4], bl[4];
            LDSM_X4(bh, sb_h);
            LDSM_X4(bl, sb_l);
            #pragma unroll
            for (int h = 0; h < 2; h++) {
                int nf = 2 * p + h;
                #pragma unroll
                for (int mb = 0; mb < 3; mb++) {
                    MMA_BF16(c[mb][nf], ah3[mb], bh[2*h], bh[2*h+1]);   // hi*hi
                    MMA_BF16(c[mb][nf], ah3[mb], bl[2*h], bl[2*h+1]);   // hi*lo
                    MMA_BF16(c[mb][nf], al3[mb], bh[2*h], bh[2*h+1]);   // lo*hi
                }
            }
        }

        // write next tile into the other buffer (disjoint from `buf` being read)
        if (it + 1 < NIT) STORE_REGS(buf ^ 1);
        __syncthreads();
    }

    int gq = lane >> 2;
    int tc = lane & 3;
    #pragma unroll
    for (int mb = 0; mb < 3; mb++) {
        int mA = mb * 48 + wm * 16 + gq;
        int mB = mA + 8;
        #pragma unroll
        for (int nf = 0; nf < 4; nf++) {
            int nc = n0 + wn * 32 + nf * 8 + 2 * tc;
            *reinterpret_cast<float2*>(&g_part[ks][mA][nc]) =
                make_float2(c[mb][nf][0], c[mb][nf][1]);
            *reinterpret_cast<float2*>(&g_part[ks][mB][nc]) =
                make_float2(c[mb][nf][2], c[mb][nf][3]);
        }
    }
}

// ---------------- kernel 4: combine partials + bias + mask + permute (float4) ----------------
__global__ void combine_kernel(const float* __restrict__ bias,
                               float* __restrict__ out) {
    int m = blockIdx.x;                               // 144
    int n4 = blockIdx.y * 256 + threadIdx.x;          // float4 index, 512 total
    int bimg = m / TOP;
    float4 v = make_float4(0.f, 0.f, 0.f, 0.f);
    if (g_valid[m]) {
        v = reinterpret_cast<const float4*>(bias)[n4];
        #pragma unroll
        for (int s = 0; s < KSPLIT; s++) {
            float4 p = reinterpret_cast<const float4*>(g_part[s][m])[n4];
            v.x += p.x;  v.y += p.y;  v.z += p.z;  v.w += p.w;
        }
    }
    reinterpret_cast<float4*>(out + ((size_t)(bimg * TOP + g_dest[m])) * Dd)[n4] = v;
}

// ---------------- launch ----------------
extern "C" void kernel_launch(void* const* d_in, const int* in_sizes, int n_in,
                              void* d_out, int out_size) {
    const float* boxes  = (const float*)d_in[0];
    const float* scores = (const float*)d_in[1];
    const float* f0     = (const float*)d_in[2];
    const float* f1     = (const float*)d_in[3];
    const float* f2     = (const float*)d_in[4];
    const float* f3     = (const float*)d_in[5];
    const float* Wm     = (const float*)d_in[6];
    const float* bias   = (const float*)d_in[7];
    float* out = (float*)d_out;

    cudaFuncSetAttribute(gemm_kernel,
                         cudaFuncAttributeMaxDynamicSharedMemorySize,
                         GEMM_SMEM_BYTES);

    select_kernel<<<Bsz, 320>>>(boxes, scores);
    schedule_kernel<<<1, 160>>>();
    pool_kernel<<<dim3(NROI, 32), 256>>>(f0, f1, f2, f3);
    gemm_kernel<<<dim3(Dd / 128, KSPLIT), 384, GEMM_SMEM_BYTES>>>(Wm);
    combine_kernel<<<dim3(NROI, 2), 256>>>(bias, out);
}

// round 16
// speedup vs baseline: 1.2161x; 1.0123x over previous
#include <cuda_runtime.h>
#include <cuda_bf16.h>

#define Bsz 4
#define Nn 300
#define TOP 36
#define Cc 2048
#define Dd 2048
#define NROI (Bsz*TOP)
#define KSPLIT 16
#define KSEG (Cc / KSPLIT)   // 128
#define NIT  (KSEG / 16)     // 8

// ---------------- scratch (device globals, no allocation) ----------------
__device__ int   g_valid[NROI];
__device__ int   g_level[NROI];
__device__ int   g_dest[NROI];
__device__ int   g_ny[NROI], g_nx[NROI];
__device__ int   g_yi[NROI][28], g_xi[NROI][28];
__device__ float g_yw[NROI][28], g_xw[NROI][28];
__device__ int   g_order[NROI];

// bf16 hi/lo decompositions of pooled features (tensor-core GEMM A operand)
__device__ __align__(16) __nv_bfloat16 g_Ph[NROI][Cc];
__device__ __align__(16) __nv_bfloat16 g_Pl[NROI][Cc];

__device__ __forceinline__ int level_size(int l) {
    return (l == 0) ? 100 : (l == 1) ? 50 : (l == 2) ? 25 : 13;
}

// split a,b into bf16 hi + bf16 residual, packed as bf16x2 words
__device__ __forceinline__ void split2(float a, float b, unsigned& h, unsigned& l) {
    __nv_bfloat16 ha = __float2bfloat16(a);
    __nv_bfloat16 hb = __float2bfloat16(b);
    float ra = a - __bfloat162float(ha);
    float rb = b - __bfloat162float(hb);
    __nv_bfloat162 H; H.x = ha; H.y = hb;
    __nv_bfloat162 L; L.x = __float2bfloat16(ra); L.y = __float2bfloat16(rb);
    h = *reinterpret_cast<unsigned*>(&H);
    l = *reinterpret_cast<unsigned*>(&L);
}

// Streaming separable axis table: 14 monotone samples -> merged (idx, weight)
// list (<=28 entries). Exactly replicates reference bilinear accumulation.
__device__ int build_axis(float start, float rlen, int Hs, int* gidx, float* gwt) {
    int   li[28];
    float lw[28];
    int n = 0;
    float step7  = rlen / 7.0f;
    float step14 = rlen / 14.0f;
    for (int i = 0; i < 14; i++) {
        float yy = start + (float)(i >> 1) * step7 + ((float)(i & 1) + 0.5f) * step14;
        if (yy < -1.0f || yy > (float)Hs) continue;
        float yc = fminf(fmaxf(yy, 0.0f), (float)Hs - 1.0f);
        int i0 = (int)floorf(yc);
        int i1 = min(i0 + 1, Hs - 1);
        float w = yc - (float)i0;
        float w0 = 1.0f - w;
        if (n > 0 && li[n-1] == i0)      lw[n-1] += w0;
        else if (n > 1 && li[n-2] == i0) lw[n-2] += w0;
        else { li[n] = i0; lw[n] = w0; n++; }
        if (n > 0 && li[n-1] == i1)      lw[n-1] += w;
        else if (n > 1 && li[n-2] == i1) lw[n-2] += w;
        else { li[n] = i1; lw[n] = w; n++; }
    }
    for (int t = 0; t < n; t++) { gidx[t] = li[t]; gwt[t] = lw[t]; }
    return n;
}

// ---------------- kernel 1: filter + sort + warp NMS + tables + dest ----------------
__global__ void select_kernel(const float* __restrict__ boxes,
                              const float* __restrict__ scores) {
    int b = blockIdx.x;
    int tid = threadIdx.x;
    __shared__ float ss[Nn];
    __shared__ float sx1[Nn], sy1[Nn], sx2[Nn], sy2[Nn];
    __shared__ int   s_selidx[TOP];
    __shared__ int   s_cnt;
    __shared__ int   s_M;
    __shared__ int   keys[TOP];

    const float* sc = scores + b * Nn;
    const float* bx = boxes + (size_t)b * Nn * 4;

    if (tid == 0) s_M = 0;
    for (int i = tid; i < Nn; i += blockDim.x) ss[i] = sc[i];
    __syncthreads();

    {
        int local = 0;
        for (int i = tid; i < Nn; i += blockDim.x) local += (ss[i] > 0.3f);
        #pragma unroll
        for (int o = 16; o; o >>= 1) local += __shfl_down_sync(0xffffffffu, local, o);
        if ((tid & 31) == 0 && local) atomicAdd(&s_M, local);
    }

    for (int i = tid; i < Nn; i += blockDim.x) {
        float si = ss[i];
        if (si > 0.3f) {
            int rank = 0;
            for (int j = 0; j < Nn; j++) {
                float sj = ss[j];
                rank += (sj > 0.3f) && ((sj > si) || (sj == si && j < i));
            }
            sx1[rank] = bx[i * 4 + 0];
            sy1[rank] = bx[i * 4 + 1];
            sx2[rank] = bx[i * 4 + 2];
            sy2[rank] = bx[i * 4 + 3];
        }
    }
    __syncthreads();

    int M = s_M;

    if (tid < 32) {
        int lane = tid;
        unsigned kmask = 0;
        #pragma unroll
        for (int s2 = 0; s2 < 10; s2++)
            if (lane + 32 * s2 < M) kmask |= (1u << s2);
        int cnt = 0;
        for (int i = 0; i < M; i++) {
            unsigned om = __shfl_sync(0xffffffffu, kmask, i & 31);
            if (!((om >> (i >> 5)) & 1u)) continue;
            if (lane == 0) s_selidx[cnt] = i;
            cnt++;
            if (cnt >= TOP) break;
            float x1 = sx1[i], y1 = sy1[i], x2 = sx2[i], y2 = sy2[i];
            float ai = (x2 - x1) * (y2 - y1);
            #pragma unroll
            for (int s2 = 0; s2 < 10; s2++) {
                int j = lane + 32 * s2;
                if (((kmask >> s2) & 1u) && j > i && j < M) {
                    float jx1 = sx1[j], jy1 = sy1[j], jx2 = sx2[j], jy2 = sy2[j];
                    float xx1 = fmaxf(x1, jx1);
                    float yy1 = fmaxf(y1, jy1);
                    float xx2 = fminf(x2, jx2);
                    float yy2 = fminf(y2, jy2);
                    float inter = fmaxf(xx2 - xx1, 0.0f) * fmaxf(yy2 - yy1, 0.0f);
                    float aj = (jx2 - jx1) * (jy2 - jy1);
                    float iou = inter / (ai + aj - inter);
                    if (iou > 0.7f) kmask &= ~(1u << s2);
                }
            }
        }
        if (lane == 0) s_cnt = cnt;
    }
    __syncthreads();

    if (tid < TOP) {
        int r = tid;
        int roi = b * TOP + r;
        int valid = 0, lvl = 0;
        if (r < s_cnt) {
            valid = 1;
            int i = s_selidx[r];
            float bx0 = sx1[i], bx1 = sy1[i], bx2 = sx2[i], bx3 = sy2[i];
            float dx = bx2 - bx0, dy = bx3 - bx1;
            float diag = sqrtf(dx * dx + dy * dy);
            float lf = floorf(4.0f + log2f(diag / 224.0f * 4.0f));
            lf = fminf(fmaxf(lf, 2.0f), 5.0f);
            lvl = (int)lf - 2;
            int Hs = level_size(lvl);
            float rw = fmaxf(bx2 - bx0, 1.0f);
            float rh = fmaxf(bx3 - bx1, 1.0f);
            g_ny[roi] = build_axis(bx1, rh, Hs, g_yi[roi], g_yw[roi]);
            g_nx[roi] = build_axis(bx0, rw, Hs, g_xi[roi], g_xw[roi]);
        } else {
            g_ny[roi] = 0;
            g_nx[roi] = 0;
        }
        g_valid[roi] = valid;
        g_level[roi] = lvl;
        keys[r] = valid ? (lvl * TOP + r) : (4 * TOP + r);
    }
    __syncthreads();
    if (tid < TOP) {
        int k = keys[tid];
        int d = 0;
        for (int q = 0; q < TOP; q++) d += (keys[q] < k);
        g_dest[b * TOP + tid] = d;
    }
}

// ---------------- kernel 1b: LPT ordering (slow level-0 rois first) ----------------
__global__ void schedule_kernel() {
    __shared__ int keys[NROI];
    int t = threadIdx.x;
    if (t < NROI) {
        int lvl = g_level[t];
        int img = t / TOP;
        keys[t] = g_valid[t] ? (lvl * 8 + img) : 1024;
    }
    __syncthreads();
    if (t < NROI) {
        int k = keys[t];
        int rank = 0;
        for (int j = 0; j < NROI; j++)
            rank += (keys[j] < k) || (keys[j] == k && j < t);
        g_order[rank] = t;
    }
}

// ---------------- kernel 1c: init output rows (bias at permuted dest, zero if invalid) ----------------
__global__ void bias_init_kernel(const float* __restrict__ bias,
                                 float* __restrict__ out) {
    int m = blockIdx.x;                               // source roi 0..143
    int n4 = blockIdx.y * 256 + threadIdx.x;          // float4 col
    int bimg = m / TOP;
    float4 v = make_float4(0.f, 0.f, 0.f, 0.f);
    if (g_valid[m]) v = reinterpret_cast<const float4*>(bias)[n4];
    reinterpret_cast<float4*>(out + ((size_t)(bimg * TOP + g_dest[m])) * Dd)[n4] = v;
}

// ---------------- kernel 2: ROI pooling (R6 tap-gather + inline bf16 hi/lo epilogue) ----------------
// grid (32, NROI): cblk varies fastest -> consecutive blocks read contiguous
// channel planes of the same roi (DRAM row locality).
__global__ void pool_kernel(const float* __restrict__ f0, const float* __restrict__ f1,
                            const float* __restrict__ f2, const float* __restrict__ f3) {
    int roi  = g_order[blockIdx.y];
    int cblk = blockIdx.x;
    int tid  = threadIdx.x;

    if (!g_valid[roi]) {
        if (tid < 64) {
            int c = cblk * 64 + tid;
            g_Ph[roi][c] = __float2bfloat16(0.0f);
            g_Pl[roi][c] = __float2bfloat16(0.0f);
        }
        return;
    }

    __shared__ int   soff[784];
    __shared__ float swt[784];

    int lvl = g_level[roi];
    int Hs  = level_size(lvl);
    int HW  = Hs * Hs;
    const float* fm = (lvl == 0) ? f0 : (lvl == 1) ? f1 : (lvl == 2) ? f2 : f3;

    int ny = g_ny[roi], nx = g_nx[roi];
    int n = ny * nx;
    for (int k = tid; k < n; k += 256) {
        int a = k / nx;
        int q = k - a * nx;
        soff[k] = g_yi[roi][a] * Hs + g_xi[roi][q];
        swt[k]  = g_yw[roi][a] * g_xw[roi][q];
    }
    __syncthreads();

    int bimg = roi / TOP;
    int warp = tid >> 5, lane = tid & 31;
    #pragma unroll
    for (int q = 0; q < 2; q++) {
        int c = cblk * 64 + (warp << 3) + (q << 2);
        const float* b0 = fm + ((size_t)(bimg * Cc + c)) * (size_t)HW;
        const float* b1 = b0 + HW;
        const float* b2 = b1 + HW;
        const float* b3 = b2 + HW;
        float a0 = 0.f, a1 = 0.f, a2 = 0.f, a3 = 0.f;
        float a4 = 0.f, a5 = 0.f, a6 = 0.f, a7 = 0.f;
        int k = lane;
        for (; k + 32 < n; k += 64) {
            int   o0 = soff[k],  o1 = soff[k + 32];
            float w0 = swt[k],   w1 = swt[k + 32];
            float v0 = b0[o0], v1 = b1[o0], v2 = b2[o0], v3 = b3[o0];
            float v4 = b0[o1], v5 = b1[o1], v6 = b2[o1], v7 = b3[o1];
            a0 += v0 * w0;  a1 += v1 * w0;  a2 += v2 * w0;  a3 += v3 * w0;
            a4 += v4 * w1;  a5 += v5 * w1;  a6 += v6 * w1;  a7 += v7 * w1;
        }
        if (k < n) {
            int o = soff[k]; float w = swt[k];
            a0 += b0[o] * w;  a1 += b1[o] * w;
            a2 += b2[o] * w;  a3 += b3[o] * w;
        }
        float s0 = a0 + a4, s1 = a1 + a5, s2 = a2 + a6, s3 = a3 + a7;
        #pragma unroll
        for (int o = 16; o; o >>= 1) {
            s0 += __shfl_down_sync(0xffffffffu, s0, o);
            s1 += __shfl_down_sync(0xffffffffu, s1, o);
            s2 += __shfl_down_sync(0xffffffffu, s2, o);
            s3 += __shfl_down_sync(0xffffffffu, s3, o);
        }
        if (lane == 0) {
            s0 *= (1.0f / 196.0f);  s1 *= (1.0f / 196.0f);
            s2 *= (1.0f / 196.0f);  s3 *= (1.0f / 196.0f);
            unsigned h0, l0, h1, l1;
            split2(s0, s1, h0, l0);
            split2(s2, s3, h1, l1);
            *reinterpret_cast<uint2*>(&g_Ph[roi][c]) = make_uint2(h0, h1);
            *reinterpret_cast<uint2*>(&g_Pl[roi][c]) = make_uint2(l0, l1);
        }
    }
}

// ---------------- kernel 3: tensor-core GEMM v6 (double-buffer, atomic epilogue) ----------------
// Block covers full M=144 (3 m-tiles of 48) x 128 n x KSEG=128 k.
// grid (Dd/128=16, KSPLIT=16) = 256 blocks x 384 threads (12 warps = 3m x 4n).
// Epilogue adds partial results directly into out at permuted dest rows via
// atomicAdd (REDG) - no g_part spill, no combine kernel. Invalid rois have
// zeroed Ph/Pl so their contributions are exactly 0.
#define MMA_BF16(c, a, b0v, b1v)                                             \
    asm volatile("mma.sync.aligned.m16n8k16.row.col.f32.bf16.bf16.f32 "      \
                 "{%0,%1,%2,%3}, {%4,%5,%6,%7}, {%8,%9}, {%0,%1,%2,%3};"     \
                 : "+f"(c[0]), "+f"(c[1]), "+f"(c[2]), "+f"(c[3])            \
                 : "r"(a[0]), "r"(a[1]), "r"(a[2]), "r"(a[3]),               \
                   "r"(b0v), "r"(b1v))

#define LDSM_X4(r, addr)                                                     \
    asm volatile("ldmatrix.sync.aligned.m8n8.x4.shared.b16 {%0,%1,%2,%3}, [%4];" \
                 : "=r"(r[0]), "=r"(r[1]), "=r"(r[2]), "=r"(r[3]) : "r"(addr))

// dynamic smem element offsets (bf16 units)
#define G_AH 0
#define G_AL (G_AH + 2 * 144 * 24)
#define G_BH (G_AL + 2 * 144 * 24)
#define G_BL (G_BH + 2 * 128 * 24)
#define GEMM_SMEM_ELEMS (G_BL + 2 * 128 * 24)
#define GEMM_SMEM_BYTES (GEMM_SMEM_ELEMS * 2)

__global__ void __launch_bounds__(384) gemm_kernel(const float* __restrict__ Wm,
                                                   float* __restrict__ out) {
    extern __shared__ __nv_bfloat16 smg[];
    __nv_bfloat16* sAh = smg + G_AH;
    __nv_bfloat16* sAl = smg + G_AL;
    __nv_bfloat16* sBh = smg + G_BH;
    __nv_bfloat16* sBl = smg + G_BL;

    int tid  = threadIdx.x;
    int wid  = tid >> 5, lane = tid & 31;
    int n0   = blockIdx.x * 128;
    int ks   = blockIdx.y;
    int kbase = ks * KSEG;

    int wm = wid % 3;
    int wn = wid / 3;
    int g  = lane >> 3;
    int r  = lane & 7;

    // fixed staging slots
    bool hasB = (tid < 256);
    int  bnn = tid >> 1, bhalf = tid & 1;              // B slot (tid<256)
    bool hasA = (tid >= 256) || (tid < 160);
    int  au = (tid >= 256) ? (tid - 256) : (tid + 128); // A slot id 0..287
    int  am = au >> 1, ahalf = au & 1;

    const float4* wsrc = hasB
        ? reinterpret_cast<const float4*>(Wm + (size_t)(n0 + bnn) * Cc + kbase + bhalf * 8)
        : nullptr;

    float4 bw0, bw1;
    uint4  par_h, par_l;

    #define LOAD_REGS(it)                                                        \
        do {                                                                     \
            if (hasB) { bw0 = wsrc[(it) * 4]; bw1 = wsrc[(it) * 4 + 1]; }        \
            if (hasA) {                                                          \
                par_h = *reinterpret_cast<const uint4*>(                         \
                    &g_Ph[am][kbase + (it) * 16 + ahalf * 8]);                   \
                par_l = *reinterpret_cast<const uint4*>(                         \
                    &g_Pl[am][kbase + (it) * 16 + ahalf * 8]);                   \
            }                                                                    \
        } while (0)

    #define STORE_REGS(nb)                                                       \
        do {                                                                     \
            if (hasB) {                                                          \
                unsigned h0, l0, h1, l1, h2, l2, h3, l3;                         \
                split2(bw0.x, bw0.y, h0, l0);                                    \
                split2(bw0.z, bw0.w, h1, l1);                                    \
                split2(bw1.x, bw1.y, h2, l2);                                    \
                split2(bw1.z, bw1.w, h3, l3);                                    \
                *reinterpret_cast<uint4*>(&sBh[(nb) * 3072 + bnn * 24 + bhalf * 8]) \
                    = make_uint4(h0, h1, h2, h3);                                \
                *reinterpret_cast<uint4*>(&sBl[(nb) * 3072 + bnn * 24 + bhalf * 8]) \
                    = make_uint4(l0, l1, l2, l3);                                \
            }                                                                    \
            if (hasA) {                                                          \
                *reinterpret_cast<uint4*>(&sAh[(nb) * 3456 + am * 24 + ahalf * 8]) = par_h; \
                *reinterpret_cast<uint4*>(&sAl[(nb) * 3456 + am * 24 + ahalf * 8]) = par_l; \
            }                                                                    \
        } while (0)

    float c[3][4][4] = {};

    LOAD_REGS(0);
    STORE_REGS(0);
    __syncthreads();

    for (int it = 0; it < NIT; it++) {
        int buf = it & 1;
        if (it + 1 < NIT) LOAD_REGS(it + 1);

        const __nv_bfloat16* bAh = sAh + buf * 3456;
        const __nv_bfloat16* bAl = sAl + buf * 3456;
        const __nv_bfloat16* bBh = sBh + buf * 3072;
        const __nv_bfloat16* bBl = sBl + buf * 3072;

        unsigned ah3[3][4], al3[3][4];
        #pragma unroll
        for (int mb = 0; mb < 3; mb++) {
            int arow = mb * 48 + wm * 16 + (g & 1) * 8 + r;
            int koff = (g >> 1) * 8;
            unsigned sa_h = (unsigned)__cvta_generic_to_shared(&bAh[arow * 24 + koff]);
            unsigned sa_l = (unsigned)__cvta_generic_to_shared(&bAl[arow * 24 + koff]);
            LDSM_X4(ah3[mb], sa_h);
            LDSM_X4(al3[mb], sa_l);
        }

        #pragma unroll
        for (int p = 0; p < 2; p++) {
            int brow = wn * 32 + p * 16 + (g >> 1) * 8 + r;
            int koff = (g & 1) * 8;
            unsigned sb_h = (unsigned)__cvta_generic_to_shared(&bBh[brow * 24 + koff]);
            unsigned sb_l = (unsigned)__cvta_generic_to_shared(&bBl[brow * 24 + koff]);
            unsigned bh[4], bl[4];
            LDSM_X4(bh, sb_h);
            LDSM_X4(bl, sb_l);
            #pragma unroll
            for (int h = 0; h < 2; h++) {
                int nf = 2 * p + h;
                #pragma unroll
                for (int mb = 0; mb < 3; mb++) {
                    MMA_BF16(c[mb][nf], ah3[mb], bh[2*h], bh[2*h+1]);   // hi*hi
                    MMA_BF16(c[mb][nf], ah3[mb], bl[2*h], bl[2*h+1]);   // hi*lo
                    MMA_BF16(c[mb][nf], al3[mb], bh[2*h], bh[2*h+1]);   // lo*hi
                }
            }
        }

        if (it + 1 < NIT) STORE_REGS(buf ^ 1);
        __syncthreads();
    }

    int gq = lane >> 2;
    int tc = lane & 3;
    #pragma unroll
    for (int mb = 0; mb < 3; mb++) {
        int mA = mb * 48 + wm * 16 + gq;
        int mB = mA + 8;
        size_t rowA = ((size_t)((mA / TOP) * TOP + g_dest[mA])) * Dd;
        size_t rowB = ((size_t)((mB / TOP) * TOP + g_dest[mB])) * Dd;
        #pragma unroll
        for (int nf = 0; nf < 4; nf++) {
            int nc = n0 + wn * 32 + nf * 8 + 2 * tc;
            atomicAdd(&out[rowA + nc],     c[mb][nf][0]);
            atomicAdd(&out[rowA + nc + 1], c[mb][nf][1]);
            atomicAdd(&out[rowB + nc],     c[mb][nf][2]);
            atomicAdd(&out[rowB + nc + 1], c[mb][nf][3]);
        }
    }
}

// ---------------- launch ----------------
extern "C" void kernel_launch(void* const* d_in, const int* in_sizes, int n_in,
                              void* d_out, int out_size) {
    const float* boxes  = (const float*)d_in[0];
    const float* scores = (const float*)d_in[1];
    const float* f0     = (const float*)d_in[2];
    const float* f1     = (const float*)d_in[3];
    const float* f2     = (const float*)d_in[4];
    const float* f3     = (const float*)d_in[5];
    const float* Wm     = (const float*)d_in[6];
    const float* bias   = (const float*)d_in[7];
    float* out = (float*)d_out;

    cudaFuncSetAttribute(gemm_kernel,
                         cudaFuncAttributeMaxDynamicSharedMemorySize,
                         GEMM_SMEM_BYTES);

    select_kernel<<<Bsz, 320>>>(boxes, scores);
    schedule_kernel<<<1, 160>>>();
    bias_init_kernel<<<dim3(NROI, 2), 256>>>(bias, out);
    pool_kernel<<<dim3(32, NROI), 256>>>(f0, f1, f2, f3);
    gemm_kernel<<<dim3(Dd / 128, KSPLIT), 384, GEMM_SMEM_BYTES>>>(Wm, out);
}